// round 5
// baseline (speedup 1.0000x reference)
#include <cuda_runtime.h>

#define NUM_NODES 50000
#define C 64
#define NUM_EDGES 800000

// Scratch (allocation-free rule: __device__ globals)
__device__ __align__(16) float g_aggr[NUM_NODES * C];
__device__ float g_deg[NUM_NODES];
__device__ __align__(16) float g_Wt[128 * 64];   // W transposed: [k][o]
__device__ int g_is64;   // 1 if edge_index buffer is int64, 0 if int32

// ---------------------------------------------------------------------------
// Kernel 1: fused prep — zero aggr/deg, transpose W, detect index width.
// Grid = 3125 blocks x 256 (covers 800000 float4 of g_aggr).
// ---------------------------------------------------------------------------
__global__ void prep_kernel(const float* __restrict__ W,
                            const long long* __restrict__ ei64) {
    int i = blockIdx.x * blockDim.x + threadIdx.x;

    // zero aggr (float4) + deg
    ((float4*)g_aggr)[i] = make_float4(0.f, 0.f, 0.f, 0.f);
    if (i < NUM_NODES) g_deg[i] = 0.f;

    // transpose W: first 32 blocks cover 8192 elements
    if (i < 64 * 128) {
        int o = i >> 7;
        int k = i & 127;
        g_Wt[k * 64 + o] = W[i];
    }

    // detect: block 0 samples 1024 int64 entries
    if (blockIdx.x == 0) {
        __shared__ int bad;
        if (threadIdx.x == 0) bad = 0;
        __syncthreads();
        for (int j = threadIdx.x; j < 1024; j += 256) {
            long long v = ei64[j];
            if (v < 0 || v >= NUM_NODES) bad = 1;
        }
        __syncthreads();
        if (threadIdx.x == 0) g_is64 = bad ? 0 : 1;
    }
}

// ---------------------------------------------------------------------------
// Kernel 2: scatter-add x[row] into g_aggr[col], count degree.
// 4 threads/edge, 4 float4 (64B) each -> MLP=4 per thread, 4x fewer
// index loads, coalesced 256B row gather per 4-lane group.
// ---------------------------------------------------------------------------
__global__ void scatter_kernel(const float* __restrict__ x,
                               const void* __restrict__ ei_raw) {
    int idx = blockIdx.x * blockDim.x + threadIdx.x;
    int e = idx >> 2;
    int q = idx & 3;            // quarter of the 256B row
    if (e >= NUM_EDGES) return;

    long long r, c;
    if (g_is64) {
        const long long* ei = (const long long*)ei_raw;
        r = __ldg(&ei[e]);
        c = __ldg(&ei[NUM_EDGES + e]);
    } else {
        const int* ei = (const int*)ei_raw;
        r = __ldg(&ei[e]);
        c = __ldg(&ei[NUM_EDGES + e]);
    }
    if (r < 0 || r >= NUM_NODES || c < 0 || c >= NUM_NODES) return;

    const float4* src = (const float4*)(x + r * C) + (q << 2);
    float4 v0 = __ldg(src + 0);
    float4 v1 = __ldg(src + 1);
    float4 v2 = __ldg(src + 2);
    float4 v3 = __ldg(src + 3);

    float* dst = g_aggr + c * C + (q << 4);
    asm volatile("red.global.add.v4.f32 [%0], {%1,%2,%3,%4};"
                 :: "l"(dst), "f"(v0.x), "f"(v0.y), "f"(v0.z), "f"(v0.w) : "memory");
    asm volatile("red.global.add.v4.f32 [%0], {%1,%2,%3,%4};"
                 :: "l"(dst + 4), "f"(v1.x), "f"(v1.y), "f"(v1.z), "f"(v1.w) : "memory");
    asm volatile("red.global.add.v4.f32 [%0], {%1,%2,%3,%4};"
                 :: "l"(dst + 8), "f"(v2.x), "f"(v2.y), "f"(v2.z), "f"(v2.w) : "memory");
    asm volatile("red.global.add.v4.f32 [%0], {%1,%2,%3,%4};"
                 :: "l"(dst + 12), "f"(v3.x), "f"(v3.y), "f"(v3.z), "f"(v3.w) : "memory");

    if (q == 0) atomicAdd(&g_deg[c], 1.0f);
}

// ---------------------------------------------------------------------------
// Kernel 3: out[n] = concat(x[n], aggr[n]*rdeg) @ W^T + b
// Register-tiled: 64 nodes x 64 outs per 256-thread block.
// Thread = 1 node x 16 outputs (8 f32x2 accumulators, fma.rn.f32x2).
// ---------------------------------------------------------------------------
#define WT_STRIDE 64
#define F_STRIDE  65
#define SMEM_WT   0
#define SMEM_F    (128 * WT_STRIDE)                 // floats
#define SMEM_RD   (SMEM_F + 128 * F_STRIDE)         // floats
#define GEMM_SMEM ((SMEM_RD + 64) * 4)              // bytes = 66304

__global__ void __launch_bounds__(256, 3)
gemm_kernel(const float* __restrict__ x,
            const float* __restrict__ b,
            float* __restrict__ out) {
    extern __shared__ float sm[];
    float* Wt   = sm + SMEM_WT;   // [k][o] stride 64
    float* F    = sm + SMEM_F;    // [k][n] stride 65
    float* rdeg = sm + SMEM_RD;   // [64]

    int t = threadIdx.x;
    int base = blockIdx.x * 64;

    // Stage W: straight copy (coalesced LDG.128, conflict-free STS.128)
    #pragma unroll
    for (int i = t; i < 128 * 64 / 4; i += 256) {
        ((float4*)Wt)[i] = ((const float4*)g_Wt)[i];
    }

    // Per-node reciprocal degree
    if (t < 64) {
        int n = base + t;
        rdeg[t] = (n < NUM_NODES) ? __frcp_rn(fmaxf(g_deg[n], 1.0f)) : 0.0f;
    }
    __syncthreads();

    // Stage features transposed: F[c][n]; coalesced gmem reads,
    // STS stride 65 -> conflict-free.
    #pragma unroll
    for (int i = t; i < 64 * 128; i += 256) {
        int nl = i >> 7;
        int c  = i & 127;
        int n  = base + nl;
        float v = 0.0f;
        if (n < NUM_NODES) {
            v = (c < C) ? x[n * C + c]
                        : g_aggr[n * C + (c - C)] * rdeg[nl];
        }
        F[c * F_STRIDE + nl] = v;
    }
    __syncthreads();

    int nl = t & 63;          // node within block
    int o0 = (t >> 6) << 4;   // output base: 0,16,32,48 (warp-uniform)
    int n  = base + nl;

    // 8 packed f32x2 accumulators = 16 outputs
    unsigned long long acc[8];
    #pragma unroll
    for (int p = 0; p < 8; p++) acc[p] = 0ULL;

    const float* frow = F + nl;
    const float* wrow = Wt + o0;

    #pragma unroll 8
    for (int k = 0; k < 128; k++) {
        float f = frow[k * F_STRIDE];
        unsigned long long fp;
        asm("mov.b64 %0, {%1, %1};" : "=l"(fp) : "f"(f));
        const ulonglong2* wv = (const ulonglong2*)(wrow + k * WT_STRIDE);
        ulonglong2 w01 = wv[0];
        ulonglong2 w23 = wv[1];
        ulonglong2 w45 = wv[2];
        ulonglong2 w67 = wv[3];
        asm("fma.rn.f32x2 %0, %1, %2, %0;" : "+l"(acc[0]) : "l"(w01.x), "l"(fp));
        asm("fma.rn.f32x2 %0, %1, %2, %0;" : "+l"(acc[1]) : "l"(w01.y), "l"(fp));
        asm("fma.rn.f32x2 %0, %1, %2, %0;" : "+l"(acc[2]) : "l"(w23.x), "l"(fp));
        asm("fma.rn.f32x2 %0, %1, %2, %0;" : "+l"(acc[3]) : "l"(w23.y), "l"(fp));
        asm("fma.rn.f32x2 %0, %1, %2, %0;" : "+l"(acc[4]) : "l"(w45.x), "l"(fp));
        asm("fma.rn.f32x2 %0, %1, %2, %0;" : "+l"(acc[5]) : "l"(w45.y), "l"(fp));
        asm("fma.rn.f32x2 %0, %1, %2, %0;" : "+l"(acc[6]) : "l"(w67.x), "l"(fp));
        asm("fma.rn.f32x2 %0, %1, %2, %0;" : "+l"(acc[7]) : "l"(w67.y), "l"(fp));
    }

    if (n >= NUM_NODES) return;

    // Unpack, add bias, store as 4 x STG.128
    float* orow = out + n * 64 + o0;
    #pragma unroll
    for (int j = 0; j < 4; j++) {
        float lo0, hi0, lo1, hi1;
        asm("mov.b64 {%0, %1}, %2;" : "=f"(lo0), "=f"(hi0) : "l"(acc[2 * j]));
        asm("mov.b64 {%0, %1}, %2;" : "=f"(lo1), "=f"(hi1) : "l"(acc[2 * j + 1]));
        float4 r;
        r.x = lo0 + b[o0 + 4 * j + 0];
        r.y = hi0 + b[o0 + 4 * j + 1];
        r.z = lo1 + b[o0 + 4 * j + 2];
        r.w = hi1 + b[o0 + 4 * j + 3];
        *(float4*)(orow + 4 * j) = r;
    }
}

// ---------------------------------------------------------------------------
extern "C" void kernel_launch(void* const* d_in, const int* in_sizes, int n_in,
                              void* d_out, int out_size) {
    const float* x   = (const float*)d_in[0];
    const void*  ei  = d_in[1];
    const float* W   = (const float*)d_in[2];
    const float* b   = (const float*)d_in[3];
    float*       out = (float*)d_out;

    cudaFuncSetAttribute(gemm_kernel,
                         cudaFuncAttributeMaxDynamicSharedMemorySize, GEMM_SMEM);

    prep_kernel<<<NUM_NODES * C / 4 / 256, 256>>>(W, (const long long*)ei);
    scatter_kernel<<<(NUM_EDGES * 4) / 256, 256>>>(x, ei);
    gemm_kernel<<<(NUM_NODES + 63) / 64, 256, GEMM_SMEM>>>(x, b, out);
}

// round 6
// speedup vs baseline: 1.1033x; 1.1033x over previous
#include <cuda_runtime.h>

#define NUM_NODES 50000
#define C 64
#define NUM_EDGES 800000

// Scratch (allocation-free rule: __device__ globals)
__device__ __align__(16) float g_aggr[NUM_NODES * C];
__device__ float g_deg[NUM_NODES];
__device__ __align__(16) float g_Wt[128 * 64];   // W transposed: [k][o]
__device__ int g_is64;   // 1 if edge_index buffer is int64, 0 if int32

// ---------------------------------------------------------------------------
// Kernel 1: fused prep — zero aggr/deg, transpose W, detect index width.
// 800 blocks x 256; each thread zeroes 4 float4.
// ---------------------------------------------------------------------------
__global__ void prep_kernel(const float* __restrict__ W,
                            const long long* __restrict__ ei64) {
    int tid = blockIdx.x * 256 + threadIdx.x;
    int i4 = tid * 4;
    const float4 z = make_float4(0.f, 0.f, 0.f, 0.f);
    #pragma unroll
    for (int j = 0; j < 4; j++)
        if (i4 + j < NUM_NODES * C / 4) ((float4*)g_aggr)[i4 + j] = z;

    if (tid < NUM_NODES) g_deg[tid] = 0.f;

    if (tid < 64 * 128) {
        int o = tid >> 7;
        int k = tid & 127;
        g_Wt[k * 64 + o] = W[tid];
    }

    if (blockIdx.x == 0) {
        __shared__ int bad;
        if (threadIdx.x == 0) bad = 0;
        __syncthreads();
        for (int j = threadIdx.x; j < 1024; j += 256) {
            long long v = ei64[j];
            if (v < 0 || v >= NUM_NODES) bad = 1;
        }
        __syncthreads();
        if (threadIdx.x == 0) g_is64 = bad ? 0 : 1;
    }
}

// ---------------------------------------------------------------------------
// Kernel 2: MEGA — block-specialized overlap of:
//   blocks [0, GX_BLOCKS): out = x @ W1^T + b   (x-half GEMM, 32 nodes/blk)
//   blocks [GX_BLOCKS, +50000): scatter-add (R4 layout: 16 lanes/edge)
// ---------------------------------------------------------------------------
#define GX_NODES 32
#define GX_BLOCKS ((NUM_NODES + GX_NODES - 1) / GX_NODES)   // 1563
#define SCAT_BLOCKS 50000
#define MEGA_SMEM ((64 * 64 + 64 * 33) * 4)                 // 24832 B

__global__ void __launch_bounds__(256, 5)
mega_kernel(const float* __restrict__ x,
            const void* __restrict__ ei_raw,
            const float* __restrict__ b,
            float* __restrict__ out) {
    if (blockIdx.x < GX_BLOCKS) {
        // ----- x-half GEMM: 32 nodes x 64 outs, thread = 1 node x 8 outs -----
        extern __shared__ float sm[];
        float* Wt = sm;               // W1^T: [k][o], k=0..63, stride 64
        float* F  = sm + 64 * 64;     // [c][n], stride 33

        int t = threadIdx.x;
        int base = blockIdx.x * GX_NODES;

        #pragma unroll
        for (int i = t; i < 64 * 64 / 4; i += 256)
            ((float4*)Wt)[i] = ((const float4*)g_Wt)[i];   // rows 0..63 of g_Wt

        #pragma unroll
        for (int i = t; i < GX_NODES * 64; i += 256) {
            int nl = i >> 6;
            int c  = i & 63;
            int n  = base + nl;
            F[c * 33 + nl] = (n < NUM_NODES) ? x[n * C + c] : 0.f;
        }
        __syncthreads();

        int nl = t & 31;
        int o0 = (t >> 5) << 3;   // 0,8,..,56 (warp-uniform)
        int n  = base + nl;

        unsigned long long acc[4] = {0ULL, 0ULL, 0ULL, 0ULL};

        const float* frow = F + nl;
        const float* wrow = Wt + o0;

        #pragma unroll 8
        for (int k = 0; k < 64; k++) {
            float f = frow[k * 33];
            unsigned long long fp;
            asm("mov.b64 %0, {%1, %1};" : "=l"(fp) : "f"(f));
            const ulonglong2* wv = (const ulonglong2*)(wrow + k * 64);
            ulonglong2 w01 = wv[0];
            ulonglong2 w23 = wv[1];
            asm("fma.rn.f32x2 %0, %1, %2, %0;" : "+l"(acc[0]) : "l"(w01.x), "l"(fp));
            asm("fma.rn.f32x2 %0, %1, %2, %0;" : "+l"(acc[1]) : "l"(w01.y), "l"(fp));
            asm("fma.rn.f32x2 %0, %1, %2, %0;" : "+l"(acc[2]) : "l"(w23.x), "l"(fp));
            asm("fma.rn.f32x2 %0, %1, %2, %0;" : "+l"(acc[3]) : "l"(w23.y), "l"(fp));
        }

        if (n >= NUM_NODES) return;

        float* orow = out + n * C + o0;
        #pragma unroll
        for (int j = 0; j < 2; j++) {
            float lo0, hi0, lo1, hi1;
            asm("mov.b64 {%0, %1}, %2;" : "=f"(lo0), "=f"(hi0) : "l"(acc[2 * j]));
            asm("mov.b64 {%0, %1}, %2;" : "=f"(lo1), "=f"(hi1) : "l"(acc[2 * j + 1]));
            float4 r;
            r.x = lo0 + b[o0 + 4 * j + 0];
            r.y = hi0 + b[o0 + 4 * j + 1];
            r.z = lo1 + b[o0 + 4 * j + 2];
            r.w = hi1 + b[o0 + 4 * j + 3];
            *(float4*)(orow + 4 * j) = r;
        }
    } else {
        // ----- scatter (exact R4 layout: 16 threads/edge, 1 float4 each) -----
        int idx = (blockIdx.x - GX_BLOCKS) * 256 + threadIdx.x;
        if (idx >= NUM_EDGES * 16) return;
        int e     = idx >> 4;
        int chunk = idx & 15;

        long long r, c;
        if (g_is64) {
            const long long* ei = (const long long*)ei_raw;
            r = __ldg(&ei[e]);
            c = __ldg(&ei[NUM_EDGES + e]);
        } else {
            const int* ei = (const int*)ei_raw;
            r = __ldg(&ei[e]);
            c = __ldg(&ei[NUM_EDGES + e]);
        }
        if (r < 0 || r >= NUM_NODES || c < 0 || c >= NUM_NODES) return;

        float4 v = __ldg(((const float4*)(x + r * C)) + chunk);
        float* dst = g_aggr + c * C + (chunk << 2);
        asm volatile("red.global.add.v4.f32 [%0], {%1,%2,%3,%4};"
                     :: "l"(dst), "f"(v.x), "f"(v.y), "f"(v.z), "f"(v.w)
                     : "memory");
        if (chunk == 0) atomicAdd(&g_deg[c], 1.0f);
    }
}

// ---------------------------------------------------------------------------
// Kernel 3: out += (aggr * rdeg) @ W2^T
// 64 nodes x 64 outs per block, thread = 1 node x 16 outs, K=64.
// ---------------------------------------------------------------------------
#define GA_SMEM ((64 * 64 + 64 * 65 + 64) * 4)   // 33280 B

__global__ void __launch_bounds__(256)
gemm_aggr_kernel(float* __restrict__ out) {
    extern __shared__ float sm[];
    float* Wt   = sm;                    // W2^T: [k][o], k=64..127
    float* F    = sm + 64 * 64;          // [c][n] stride 65
    float* rdeg = sm + 64 * 64 + 64 * 65;

    int t = threadIdx.x;
    int base = blockIdx.x * 64;

    #pragma unroll
    for (int i = t; i < 64 * 64 / 4; i += 256)
        ((float4*)Wt)[i] = ((const float4*)(g_Wt + 64 * 64))[i];  // rows 64..127

    if (t < 64) {
        int n = base + t;
        rdeg[t] = (n < NUM_NODES) ? __frcp_rn(fmaxf(g_deg[n], 1.0f)) : 0.0f;
    }
    __syncthreads();

    #pragma unroll
    for (int i = t; i < 64 * 64; i += 256) {
        int nl = i >> 6;
        int c  = i & 63;
        int n  = base + nl;
        F[c * 65 + nl] = (n < NUM_NODES) ? g_aggr[n * C + c] * rdeg[nl] : 0.f;
    }
    __syncthreads();

    int nl = t & 63;
    int o0 = (t >> 6) << 4;   // 0,16,32,48 (warp-uniform)
    int n  = base + nl;

    unsigned long long acc[8];
    #pragma unroll
    for (int p = 0; p < 8; p++) acc[p] = 0ULL;

    const float* frow = F + nl;
    const float* wrow = Wt + o0;

    #pragma unroll 8
    for (int k = 0; k < 64; k++) {
        float f = frow[k * 65];
        unsigned long long fp;
        asm("mov.b64 %0, {%1, %1};" : "=l"(fp) : "f"(f));
        const ulonglong2* wv = (const ulonglong2*)(wrow + k * 64);
        ulonglong2 w01 = wv[0];
        ulonglong2 w23 = wv[1];
        ulonglong2 w45 = wv[2];
        ulonglong2 w67 = wv[3];
        asm("fma.rn.f32x2 %0, %1, %2, %0;" : "+l"(acc[0]) : "l"(w01.x), "l"(fp));
        asm("fma.rn.f32x2 %0, %1, %2, %0;" : "+l"(acc[1]) : "l"(w01.y), "l"(fp));
        asm("fma.rn.f32x2 %0, %1, %2, %0;" : "+l"(acc[2]) : "l"(w23.x), "l"(fp));
        asm("fma.rn.f32x2 %0, %1, %2, %0;" : "+l"(acc[3]) : "l"(w23.y), "l"(fp));
        asm("fma.rn.f32x2 %0, %1, %2, %0;" : "+l"(acc[4]) : "l"(w45.x), "l"(fp));
        asm("fma.rn.f32x2 %0, %1, %2, %0;" : "+l"(acc[5]) : "l"(w45.y), "l"(fp));
        asm("fma.rn.f32x2 %0, %1, %2, %0;" : "+l"(acc[6]) : "l"(w67.x), "l"(fp));
        asm("fma.rn.f32x2 %0, %1, %2, %0;" : "+l"(acc[7]) : "l"(w67.y), "l"(fp));
    }

    if (n >= NUM_NODES) return;

    float* orow = out + n * C + o0;
    #pragma unroll
    for (int j = 0; j < 4; j++) {
        float lo0, hi0, lo1, hi1;
        asm("mov.b64 {%0, %1}, %2;" : "=f"(lo0), "=f"(hi0) : "l"(acc[2 * j]));
        asm("mov.b64 {%0, %1}, %2;" : "=f"(lo1), "=f"(hi1) : "l"(acc[2 * j + 1]));
        float4 r = *(float4*)(orow + 4 * j);
        r.x += lo0; r.y += hi0; r.z += lo1; r.w += hi1;
        *(float4*)(orow + 4 * j) = r;
    }
}

// ---------------------------------------------------------------------------
extern "C" void kernel_launch(void* const* d_in, const int* in_sizes, int n_in,
                              void* d_out, int out_size) {
    const float* x   = (const float*)d_in[0];
    const void*  ei  = d_in[1];
    const float* W   = (const float*)d_in[2];
    const float* b   = (const float*)d_in[3];
    float*       out = (float*)d_out;

    prep_kernel<<<800, 256>>>(W, (const long long*)ei);
    mega_kernel<<<GX_BLOCKS + SCAT_BLOCKS, 256, MEGA_SMEM>>>(x, ei, b, out);
    gemm_aggr_kernel<<<(NUM_NODES + 63) / 64, 256, GA_SMEM>>>(out);
}